// round 9
// baseline (speedup 1.0000x reference)
#include <cuda_runtime.h>
#include <cuda_fp16.h>
#include <cstdint>

#define D_MODEL   256
#define N_EXP     16
#define MAX_B     65536

// ---------------------------------------------------------------------------
// Device-global scratch (allocation-free rule)
// ---------------------------------------------------------------------------
__device__ __half   g_Ah[(size_t)MAX_B * D_MODEL];              // fp16(rn) x, [b][k]
__device__ __half   g_Bh[(size_t)N_EXP * D_MODEL * D_MODEL];    // fp16(rn) w, TRANSPOSED [e][n][k]
__device__ float    g_coef[(size_t)MAX_B * N_EXP];
__device__ unsigned g_maskbits[MAX_B / 256];

// ---------------------------------------------------------------------------
// Helpers
// ---------------------------------------------------------------------------
__device__ __forceinline__ uint32_t smem_u32(const void* p) {
    return (uint32_t)__cvta_generic_to_shared(p);
}
__device__ __forceinline__ void cp_async16(void* smem_dst, const void* gmem_src) {
    asm volatile("cp.async.cg.shared.global [%0], [%1], 16;\n"
                 :: "r"(smem_u32(smem_dst)), "l"(gmem_src));
}
__device__ __forceinline__ void cp_commit() {
    asm volatile("cp.async.commit_group;\n");
}
__device__ __forceinline__ void cp_wait1() {
    asm volatile("cp.async.wait_group 1;\n");
}
__device__ __forceinline__ void cp_wait0() {
    asm volatile("cp.async.wait_group 0;\n");
}
// Legacy fp16 tensor-core MMA (sm_80+, valid on base sm_100):
// D[16x8](f32) += A[16x16](f16) * B[16x8](f16)
__device__ __forceinline__ void mma_f16(float& c0, float& c1, float& c2, float& c3,
                                        uint32_t a0, uint32_t a1, uint32_t a2, uint32_t a3,
                                        uint32_t b0, uint32_t b1) {
    asm volatile(
        "mma.sync.aligned.m16n8k16.row.col.f32.f16.f16.f32 "
        "{%0,%1,%2,%3}, {%4,%5,%6,%7}, {%8,%9}, {%0,%1,%2,%3};\n"
        : "+f"(c0), "+f"(c1), "+f"(c2), "+f"(c3)
        : "r"(a0), "r"(a1), "r"(a2), "r"(a3), "r"(b0), "r"(b1));
}

// ---------------------------------------------------------------------------
// Kernel: zero block masks
// ---------------------------------------------------------------------------
__global__ void zero_mask_kernel(int n) {
    int i = blockIdx.x * 256 + threadIdx.x;
    if (i < n) g_maskbits[i] = 0u;
}

// ---------------------------------------------------------------------------
// Kernel: gating (one warp per token) — proven Rounds 1-5
// ---------------------------------------------------------------------------
__global__ void gate_kernel(const float* __restrict__ x,
                            const float* __restrict__ gw,
                            const float* __restrict__ gb,
                            int B) {
    __shared__ float s_gw[N_EXP * D_MODEL];
    __shared__ float s_gb[N_EXP];
    int tid = threadIdx.x;
    for (int i = tid; i < N_EXP * D_MODEL; i += 256) s_gw[i] = gw[i];
    if (tid < N_EXP) s_gb[tid] = gb[tid];
    __syncthreads();

    int warp = tid >> 5, lane = tid & 31;
    int token = blockIdx.x * 8 + warp;
    if (token >= B) return;

    const float* xr = x + (size_t)token * D_MODEL;
    float xv[8];
#pragma unroll
    for (int i = 0; i < 8; i++) xv[i] = xr[lane + 32 * i];

    float logits[N_EXP];
#pragma unroll
    for (int e = 0; e < N_EXP; e++) {
        float p = 0.f;
#pragma unroll
        for (int i = 0; i < 8; i++) p += xv[i] * s_gw[e * D_MODEL + lane + 32 * i];
#pragma unroll
        for (int off = 16; off > 0; off >>= 1) p += __shfl_xor_sync(0xffffffffu, p, off);
        logits[e] = p + s_gb[e];
    }
    float mx = logits[0]; int amax = 0;
#pragma unroll
    for (int e = 1; e < N_EXP; e++) if (logits[e] > mx) { mx = logits[e]; amax = e; }
    float sum = 0.f;
#pragma unroll
    for (int e = 0; e < N_EXP; e++) { logits[e] = expf(logits[e] - mx); sum += logits[e]; }
    float inv = 1.f / sum;
    if (lane < N_EXP) g_coef[(size_t)token * N_EXP + lane] = logits[lane] * inv;
    if (lane == 0)    atomicOr(&g_maskbits[token >> 8], 1u << amax);
}

// ---------------------------------------------------------------------------
// Kernel: prep A  (x f32 -> fp16 rn, same [b][k] layout)
// ---------------------------------------------------------------------------
__global__ void prep_A_kernel(const float* __restrict__ x, int n4) {
    int i = blockIdx.x * 256 + threadIdx.x;
    if (i >= n4) return;
    float4 v = ((const float4*)x)[i];
    union { __half h[4]; uint2 u; } p;
    p.h[0] = __float2half_rn(v.x); p.h[1] = __float2half_rn(v.y);
    p.h[2] = __float2half_rn(v.z); p.h[3] = __float2half_rn(v.w);
    ((uint2*)g_Ah)[i] = p.u;
}

// ---------------------------------------------------------------------------
// Kernel: prep B  (w[k, e*256+n] f32 -> fp16, TRANSPOSED to g_Bh[e][n][k])
//   grid = 16 * 8 * 8 blocks (e, kblk, nblk), 256 threads, 32x32 tile
// ---------------------------------------------------------------------------
__global__ void prep_B_kernel(const float* __restrict__ w) {
    __shared__ float tile[32][33];
    int bid = blockIdx.x;
    int e = bid >> 6, kb = (bid >> 3) & 7, nb = bid & 7;
    int k0 = kb * 32, n0 = nb * 32;
    int t = threadIdx.x;
    {
        int ki = t >> 5, nj = t & 31;
#pragma unroll
        for (int it = 0; it < 4; it++)
            tile[ki + it * 8][nj] =
                w[(size_t)(k0 + ki + it * 8) * (N_EXP * D_MODEL) + e * D_MODEL + n0 + nj];
    }
    __syncthreads();
    {
        int n = t >> 3, part = t & 7;
        union { __half h[4]; uint2 u; } p;
#pragma unroll
        for (int j = 0; j < 4; j++) p.h[j] = __float2half_rn(tile[part * 4 + j][n]);
        *(uint2*)(g_Bh + (size_t)(e * D_MODEL + n0 + n) * D_MODEL + k0 + part * 4) = p.u;
    }
}

// ---------------------------------------------------------------------------
// Main kernel: legacy fp16 HMMA MoE GEMM (m16n8k16).
//   CTA = 128 tokens x 128 out-cols, 256 threads (8 warps, warp tile 64x32).
//   A tile (128x256 fp16) SMEM-resident, reused by all 16 experts.
//   B slab per (e, kc) = 128n x 32k fp16 [n][k], 3-buffer cp.async ring.
//   Per expert: cfrag += A@B_e; at expert end: out += coef[row,e]*cfrag.
// ---------------------------------------------------------------------------
#define AS32 132     // A row stride in b32 (264 halfs, 528B); 132%32==4 -> conflict-free
#define BS32 36      // B n-row stride in b32 (72 halfs, 144B); 36%32==4 -> conflict-free
#define CSTRIDE 17
#define SM_A   0                                   // 128 * 528  = 67584 B
#define SM_B   67584                               // 3 * 128*144 = 55296 B
#define SM_C   122880                              // 128*17*4    = 8704 B
#define SMEM_BYTES 131584

__global__ void __launch_bounds__(256, 1)
moe_mma_kernel(float* __restrict__ out, int B) {
    extern __shared__ char sm[];
    uint32_t* s_a32 = (uint32_t*)(sm + SM_A);
    float*    s_c   = (float*)(sm + SM_C);

    const int tid  = threadIdx.x;
    const int wid  = tid >> 5;
    const int lane = tid & 31;
    const int gid  = lane >> 2;          // 0..7
    const int tig  = lane & 3;           // 0..3
    const int warp_m = wid & 1;          // 64 rows each
    const int warp_n = wid >> 1;         // 32 cols each

    const int mblk  = blockIdx.x >> 1;
    const int nhalf = blockIdx.x & 1;
    const size_t t0 = (size_t)mblk * 128;

    // ---- coefficients (masked) into SMEM ----
    {
        unsigned mb = g_maskbits[(unsigned)(t0 >> 8)];
#pragma unroll
        for (int it = 0; it < 8; it++) {
            int idx = it * 256 + tid;
            int r = idx >> 4, e = idx & 15;
            float c = g_coef[(t0 + r) * N_EXP + e];
            s_c[r * CSTRIDE + e] = ((mb >> e) & 1u) ? c : 0.f;
        }
    }

    // ---- A tile: 128 rows x 512B via cp.async (32 chunks/row) ----
    {
        const char* asrc = (const char*)(g_Ah + t0 * D_MODEL);
#pragma unroll
        for (int it = 0; it < 16; it++) {
            int idx = it * 256 + tid;            // 4096 chunks
            int r = idx >> 5, c = idx & 31;
            cp_async16(sm + SM_A + r * 528 + c * 16, asrc + (size_t)r * 512 + c * 16);
        }
    }
    // ---- slab issue: i = (e = i>>3, kc = i&7): 128 n-rows x 32 k-halfs ----
    auto issue_slab = [&](int i) {
        int e = i >> 3, kc = i & 7;
        char* dst = sm + SM_B + (i % 3) * (128 * 144);
        const char* src = (const char*)(g_Bh
            + (size_t)(e * D_MODEL + nhalf * 128) * D_MODEL + kc * 32);
#pragma unroll
        for (int it = 0; it < 2; it++) {
            int idx = it * 256 + tid;            // 512 chunks
            int n = idx >> 2, c = idx & 3;
            cp_async16(dst + n * 144 + c * 16, src + (size_t)n * 512 + c * 16);
        }
        cp_commit();
    };
    issue_slab(0);   // group: {A + slab0}

    float o[4][4][4];
#pragma unroll
    for (int mt = 0; mt < 4; mt++)
#pragma unroll
        for (int nt = 0; nt < 4; nt++)
#pragma unroll
            for (int j = 0; j < 4; j++) o[mt][nt][j] = 0.f;

    float cf[4][4][4];

#pragma unroll 1
    for (int i = 0; i < 128; i++) {
        const int kc = i & 7;
        if (i + 1 < 128) { issue_slab(i + 1); cp_wait1(); }
        else             { cp_wait0(); }
        __syncthreads();

        if (kc == 0) {
#pragma unroll
            for (int mt = 0; mt < 4; mt++)
#pragma unroll
                for (int nt = 0; nt < 4; nt++)
#pragma unroll
                    for (int j = 0; j < 4; j++) cf[mt][nt][j] = 0.f;
        }

        const uint32_t* bb = (const uint32_t*)(sm + SM_B + (i % 3) * (128 * 144));

#pragma unroll
        for (int k16 = 0; k16 < 2; k16++) {
            const int kb = kc * 16 + k16 * 8;     // b32 offset into A row
            uint32_t a[4][4];
#pragma unroll
            for (int mt = 0; mt < 4; mt++) {
                int r0 = warp_m * 64 + mt * 16 + gid;
                int base = r0 * AS32 + kb + tig;
                a[mt][0] = s_a32[base];
                a[mt][1] = s_a32[base + 8 * AS32];
                a[mt][2] = s_a32[base + 4];
                a[mt][3] = s_a32[base + 4 + 8 * AS32];
            }
            uint32_t b[4][2];
#pragma unroll
            for (int nt = 0; nt < 4; nt++) {
                int col = warp_n * 32 + nt * 8 + gid;
                int bbase = col * BS32 + k16 * 8 + tig;
                b[nt][0] = bb[bbase];
                b[nt][1] = bb[bbase + 4];
            }
#pragma unroll
            for (int mt = 0; mt < 4; mt++)
#pragma unroll
                for (int nt = 0; nt < 4; nt++)
                    mma_f16(cf[mt][nt][0], cf[mt][nt][1], cf[mt][nt][2], cf[mt][nt][3],
                            a[mt][0], a[mt][1], a[mt][2], a[mt][3],
                            b[nt][0], b[nt][1]);
        }

        if (kc == 7) {
            const int e = i >> 3;
#pragma unroll
            for (int mt = 0; mt < 4; mt++) {
                int r0 = warp_m * 64 + mt * 16 + gid;
                float c0 = s_c[r0 * CSTRIDE + e];
                float c1 = s_c[(r0 + 8) * CSTRIDE + e];
#pragma unroll
                for (int nt = 0; nt < 4; nt++) {
                    o[mt][nt][0] = fmaf(c0, cf[mt][nt][0], o[mt][nt][0]);
                    o[mt][nt][1] = fmaf(c0, cf[mt][nt][1], o[mt][nt][1]);
                    o[mt][nt][2] = fmaf(c1, cf[mt][nt][2], o[mt][nt][2]);
                    o[mt][nt][3] = fmaf(c1, cf[mt][nt][3], o[mt][nt][3]);
                }
            }
        }
    }

    // ---- epilogue: float2 stores ----
#pragma unroll
    for (int mt = 0; mt < 4; mt++) {
        size_t r0 = t0 + warp_m * 64 + mt * 16 + gid;
#pragma unroll
        for (int nt = 0; nt < 4; nt++) {
            int col = nhalf * 128 + warp_n * 32 + nt * 8 + 2 * tig;
            *(float2*)(out + r0 * D_MODEL + col)       = make_float2(o[mt][nt][0], o[mt][nt][1]);
            *(float2*)(out + (r0 + 8) * D_MODEL + col) = make_float2(o[mt][nt][2], o[mt][nt][3]);
        }
    }
}

// ---------------------------------------------------------------------------
// Launch
// ---------------------------------------------------------------------------
extern "C" void kernel_launch(void* const* d_in, const int* in_sizes, int n_in,
                              void* d_out, int out_size) {
    const float* x  = (const float*)d_in[0];
    const float* w  = (const float*)d_in[1];
    const float* gw = (const float*)d_in[2];
    const float* gb = (const float*)d_in[3];
    float* out = (float*)d_out;

    int B = in_sizes[0] / D_MODEL;
    int nblk256 = B / 256;

    zero_mask_kernel<<<(nblk256 + 255) / 256, 256>>>(nblk256);
    gate_kernel<<<B / 8, 256>>>(x, gw, gb, B);

    int nA4 = (B * D_MODEL) / 4;
    prep_A_kernel<<<(nA4 + 255) / 256, 256>>>(x, nA4);
    prep_B_kernel<<<N_EXP * 8 * 8, 256>>>(w);

    cudaFuncSetAttribute(moe_mma_kernel,
                         cudaFuncAttributeMaxDynamicSharedMemorySize, SMEM_BYTES);
    moe_mma_kernel<<<(B / 128) * 2, 256, SMEM_BYTES>>>(out, B);
}